// round 8
// baseline (speedup 1.0000x reference)
#include <cuda_runtime.h>
#include <math.h>

#define V_   10475
#define J_   55
#define B_   512
#define V3_  (V_*3)     // 31425
#define K486 486

#define TV 16   // vertices per block (main kernel)
#define TB 64   // batches per block (= 32 pairs)
#define KT 32   // K-chunk

typedef unsigned long long u64;

__device__ __forceinline__ u64 pack2(float lo, float hi) {
    u64 r;
    asm("mov.b64 %0, {%1, %2};" : "=l"(r) : "r"(__float_as_uint(lo)), "r"(__float_as_uint(hi)));
    return r;
}
__device__ __forceinline__ void unpack2(u64 v, float& lo, float& hi) {
    unsigned int a, b;
    asm("mov.b64 {%0, %1}, %2;" : "=r"(a), "=r"(b) : "l"(v));
    lo = __uint_as_float(a); hi = __uint_as_float(b);
}
__device__ __forceinline__ u64 fma2(u64 a, u64 b, u64 c) {
    u64 d;
    asm("fma.rn.f32x2 %0, %1, %2, %3;" : "=l"(d) : "l"(a), "l"(b), "l"(c));
    return d;
}

// -------- device scratch (no allocations allowed) --------
__device__ __align__(16) float g_vbase[V_*3];
__device__ float g_yoff;
__device__ float g_Jbase[J_*3];
__device__ float g_JE[J_*3*10];
__device__ __align__(16) float g_pf_t[K486*B_];     // transposed pose_feature: [k][b]
__device__ __align__(16) float g_A[B_*J_*12];       // per-joint 3x4 skinning matrices

// ============== Kernel 1: vbase = v_template + shapedirs @ shape ==============
__global__ void k_vbase(const float* __restrict__ vt,
                        const float* __restrict__ shapedirs,
                        const float* __restrict__ shape)
{
    int i = blockIdx.x*256 + threadIdx.x;
    if (i < V3_) {
        float acc = vt[i];
        #pragma unroll
        for (int s = 0; s < 10; s++) acc += shape[s] * shapedirs[i*10 + s];
        g_vbase[i] = acc;
    }
}

// ============== Kernel 2: y offset = -min(v_template[:,1]) ==============
__global__ void k_ymin(const float* __restrict__ vt)
{
    __shared__ float red[1024];
    float m = 1e30f;
    for (int v = threadIdx.x; v < V_; v += 1024) m = fminf(m, vt[v*3 + 1]);
    red[threadIdx.x] = m;
    __syncthreads();
    for (int s = 512; s > 0; s >>= 1) {
        if (threadIdx.x < s) red[threadIdx.x] = fminf(red[threadIdx.x], red[threadIdx.x + s]);
        __syncthreads();
    }
    if (threadIdx.x == 0) g_yoff = -red[0];
}

// ============== Kernel 3: Jbase(j,c) and JE(j,c,e) = JR @ [vbase | exprdirs] ==============
__global__ void k_jreg(const float* __restrict__ JR,
                       const float* __restrict__ exprdirs)
{
    int j = blockIdx.x;
    int tid = threadIdx.x;            // 128 threads
    float acc[33];
    #pragma unroll
    for (int i = 0; i < 33; i++) acc[i] = 0.f;

    for (int v = tid; v < V_; v += 128) {
        float jr = JR[j*V_ + v];
        acc[0] += jr * g_vbase[v*3 + 0];
        acc[1] += jr * g_vbase[v*3 + 1];
        acc[2] += jr * g_vbase[v*3 + 2];
        const float* ed = &exprdirs[v*30];
        #pragma unroll
        for (int i = 0; i < 30; i++) acc[3+i] += jr * ed[i];
    }
    __shared__ float red[4][33];
    int lane = tid & 31, w = tid >> 5;
    #pragma unroll
    for (int i = 0; i < 33; i++) {
        float v = acc[i];
        for (int off = 16; off > 0; off >>= 1) v += __shfl_down_sync(0xffffffffu, v, off);
        if (lane == 0) red[w][i] = v;
    }
    __syncthreads();
    if (tid < 33) {
        float s = red[0][tid] + red[1][tid] + red[2][tid] + red[3][tid];
        if (tid < 3) g_Jbase[j*3 + tid] = s;
        else         g_JE[j*30 + (tid-3)] = s;
    }
}

// ============== Kernel 4: per-batch rodrigues, pose_feature, joints, chain, A ==============
__global__ void k_pose(const float* __restrict__ body,
                       const float* __restrict__ hand,
                       const float* __restrict__ head,
                       const float* __restrict__ pelvis,
                       const float* __restrict__ hand_mean,
                       const float* __restrict__ expression)
{
    int b = blockIdx.x;
    int tid = threadIdx.x;            // 64 threads
    __shared__ float R_s[J_][9];
    __shared__ float jnt[J_][3];

    if (tid < J_) {
        float r0, r1, r2;
        if (tid == 0) {
            r0 = pelvis[b*3+0]; r1 = pelvis[b*3+1]; r2 = pelvis[b*3+2];
        } else if (tid <= 21) {
            int i = tid - 1;
            r0 = body[(b*21+i)*3+0]; r1 = body[(b*21+i)*3+1]; r2 = body[(b*21+i)*3+2];
        } else if (tid <= 24) {
            int i = tid - 22;
            r0 = head[(b*3+i)*3+0]; r1 = head[(b*3+i)*3+1]; r2 = head[(b*3+i)*3+2];
        } else {
            int h = tid - 25;
            r0 = hand[(b*30+h)*3+0] + hand_mean[h*3+0];
            r1 = hand[(b*30+h)*3+1] + hand_mean[h*3+1];
            r2 = hand[(b*30+h)*3+2] + hand_mean[h*3+2];
        }
        float a2  = r0*r0 + r1*r1 + r2*r2 + 1e-12f;
        float ang = sqrtf(a2);
        float inv = 1.0f / ang;
        float kx = r0*inv, ky = r1*inv, kz = r2*inv;
        float s = sinf(ang), c = cosf(ang);
        float t1 = 1.0f - c;
        float R[9];
        R[0] = c + t1*kx*kx;     R[1] = t1*kx*ky - s*kz;  R[2] = t1*kx*kz + s*ky;
        R[3] = t1*kx*ky + s*kz;  R[4] = c + t1*ky*ky;     R[5] = t1*ky*kz - s*kx;
        R[6] = t1*kx*kz - s*ky;  R[7] = t1*ky*kz + s*kx;  R[8] = c + t1*kz*kz;
        #pragma unroll
        for (int i = 0; i < 9; i++) R_s[tid][i] = R[i];
        if (tid >= 1) {
            #pragma unroll
            for (int i = 0; i < 9; i++) {
                float d = (i == 0 || i == 4 || i == 8) ? 1.0f : 0.0f;
                g_pf_t[((tid-1)*9 + i)*B_ + b] = R[i] - d;
            }
        }
        #pragma unroll
        for (int cc = 0; cc < 3; cc++) {
            float acc = g_Jbase[tid*3 + cc];
            #pragma unroll
            for (int e = 0; e < 10; e++)
                acc += expression[b*10 + e] * g_JE[(tid*3 + cc)*10 + e];
            jnt[tid][cc] = acc;
        }
    }
    __syncthreads();

    if (tid < 3) {
        int r = tid;
        float g0 = R_s[0][r*3+0], g1 = R_s[0][r*3+1], g2 = R_s[0][r*3+2], g3 = jnt[0][r];
        g_A[(b*J_ + 0)*12 + r*4 + 0] = g0;
        g_A[(b*J_ + 0)*12 + r*4 + 1] = g1;
        g_A[(b*J_ + 0)*12 + r*4 + 2] = g2;
        g_A[(b*J_ + 0)*12 + r*4 + 3] = g3 - (g0*jnt[0][0] + g1*jnt[0][1] + g2*jnt[0][2]);
        for (int j = 1; j < J_; j++) {
            float t0 = jnt[j][0] - jnt[j-1][0];
            float t1 = jnt[j][1] - jnt[j-1][1];
            float t2 = jnt[j][2] - jnt[j-1][2];
            float n0 = g0*R_s[j][0] + g1*R_s[j][3] + g2*R_s[j][6];
            float n1 = g0*R_s[j][1] + g1*R_s[j][4] + g2*R_s[j][7];
            float n2 = g0*R_s[j][2] + g1*R_s[j][5] + g2*R_s[j][8];
            float n3 = g0*t0 + g1*t1 + g2*t2 + g3;
            g0 = n0; g1 = n1; g2 = n2; g3 = n3;
            g_A[(b*J_ + j)*12 + r*4 + 0] = g0;
            g_A[(b*J_ + j)*12 + r*4 + 1] = g1;
            g_A[(b*J_ + j)*12 + r*4 + 2] = g2;
            g_A[(b*J_ + j)*12 + r*4 + 3] = g3 - (g0*jnt[j][0] + g1*jnt[j][1] + g2*jnt[j][2]);
        }
    }
}

// ============== Kernel 5: fused GEMM + expression + LBS + epilogue, f32x2 packed ==============
// Batch-pair packing: pair pp holds batches (b0+2pp, b0+2pp+1). Thread (vx, by)
// owns vertex vx and pairs {by, by+16} -> tile-local batches {2by,2by+1,2by+32,2by+33}.
__global__ void __launch_bounds__(256, 2)
k_main(const float* __restrict__ posedirs,
       const float* __restrict__ lbsw,
       const float* __restrict__ exprdirs,
       const float* __restrict__ expression,
       const float* __restrict__ gtrans,
       float* __restrict__ out)
{
    // phase-A tiles and phase-C tiles never live at the same time -> union
    __shared__ __align__(16) union {
        struct {
            float2 pf2[32][34];     // [pair][k], padded row (34*8=272B, 16B-aligned rows)
            float4 pd4[KT][TV];     // [k][vertex] = (x,y,z,unused)
        } a;
        float2 A2[8][32][12];       // [jj][pair][q]: lo=even batch, hi=odd batch
    } U;
    __shared__ float  ed_s[TV][30];
    __shared__ float  ex_s[TB][10];
    __shared__ __align__(16) float2 W2_s[TV][56];   // duplicated weights (w,w)
    __shared__ float  vb_s[TV][3];

    const int v0 = blockIdx.x * TV;
    const int b0 = blockIdx.y * TB;
    const int tid = threadIdx.x;
    const int vx = tid & 15;
    const int by = tid >> 4;       // 0..15

    // ---- one-time tile loads ----
    for (int i = tid; i < TV*56; i += 256) {
        int vv = i / 56, j = i % 56;
        float w = 0.f;
        if (j < J_ && v0 + vv < V_) w = lbsw[(v0+vv)*J_ + j];
        W2_s[vv][j] = make_float2(w, w);
    }
    for (int i = tid; i < TV*30; i += 256) {
        int vv = i / 30, e = i % 30;
        ed_s[vv][e] = (v0 + vv < V_) ? exprdirs[(v0+vv)*30 + e] : 0.f;
    }
    for (int i = tid; i < TB*10; i += 256)
        ex_s[i/10][i%10] = expression[(b0 + i/10)*10 + (i%10)];
    for (int i = tid; i < TV*3; i += 256)
        vb_s[i/3][i%3] = (v0 + i/3 < V_) ? g_vbase[(v0 + i/3)*3 + (i%3)] : 0.f;

    // ---- phase A: delta(pair, c) = PF @ posedirs, packed over batch pairs ----
    u64 acc[2][3];
    #pragma unroll
    for (int p = 0; p < 2; p++)
        #pragma unroll
        for (int c = 0; c < 3; c++) acc[p][c] = pack2(0.f, 0.f);

    for (int k0 = 0; k0 < K486; k0 += KT) {
        __syncthreads();
        // pf: [pair][k] float2, read batch-pairs straight out of g_pf_t
        for (int i = tid; i < 32*KT; i += 256) {
            int k = i >> 5, pp = i & 31;
            float2 v = make_float2(0.f, 0.f);
            if (k0 + k < K486)
                v = *reinterpret_cast<const float2*>(&g_pf_t[(k0+k)*B_ + b0 + 2*pp]);
            U.a.pf2[pp][k] = v;
        }
        // pd: [k][vertex] float4 (x,y,z,pad)
        for (int i = tid; i < KT*TV*3; i += 256) {
            int k = i / 48, c = i % 48;
            int vv = c / 3, cc = c % 3;
            int col = v0*3 + c;
            float val = (k0 + k < K486 && col < V3_) ? posedirs[(size_t)(k0+k)*V3_ + col] : 0.f;
            reinterpret_cast<float*>(&U.a.pd4[k][vv])[cc] = val;
        }
        __syncthreads();

        #pragma unroll
        for (int kk = 0; kk < KT; kk += 2) {
            float4 pA = U.a.pd4[kk][vx];
            float4 pB = U.a.pd4[kk+1][vx];
            longlong2 f0 = *reinterpret_cast<const longlong2*>(&U.a.pf2[by][kk]);      // pair by:    k, k+1
            longlong2 f1 = *reinterpret_cast<const longlong2*>(&U.a.pf2[by+16][kk]);   // pair by+16: k, k+1

            u64 P0a = pack2(pA.x, pA.x), P1a = pack2(pA.y, pA.y), P2a = pack2(pA.z, pA.z);
            u64 P0b = pack2(pB.x, pB.x), P1b = pack2(pB.y, pB.y), P2b = pack2(pB.z, pB.z);

            u64 f0a = (u64)f0.x, f0b = (u64)f0.y;
            u64 f1a = (u64)f1.x, f1b = (u64)f1.y;

            acc[0][0] = fma2(f0a, P0a, acc[0][0]);
            acc[0][1] = fma2(f0a, P1a, acc[0][1]);
            acc[0][2] = fma2(f0a, P2a, acc[0][2]);
            acc[1][0] = fma2(f1a, P0a, acc[1][0]);
            acc[1][1] = fma2(f1a, P1a, acc[1][1]);
            acc[1][2] = fma2(f1a, P2a, acc[1][2]);
            acc[0][0] = fma2(f0b, P0b, acc[0][0]);
            acc[0][1] = fma2(f0b, P1b, acc[0][1]);
            acc[0][2] = fma2(f0b, P2b, acc[0][2]);
            acc[1][0] = fma2(f1b, P0b, acc[1][0]);
            acc[1][1] = fma2(f1b, P1b, acc[1][1]);
            acc[1][2] = fma2(f1b, P2b, acc[1][2]);
        }
    }

    // unpack delta: bi -> tile-local batch {2by, 2by+1, 2by+32, 2by+33}
    float d[4][3];
    #pragma unroll
    for (int p = 0; p < 2; p++)
        #pragma unroll
        for (int c = 0; c < 3; c++) {
            float lo, hi;
            unpack2(acc[p][c], lo, hi);
            d[p*2+0][c] = lo; d[p*2+1][c] = hi;
        }

    // ---- phase B: v_posed = vbase + delta + exprdirs . expression ----
    float px[4], py[4], pz[4];
    #pragma unroll
    for (int bi = 0; bi < 4; bi++) {
        int bb = 2*by + (bi >> 1)*32 + (bi & 1);
        float x = vb_s[vx][0] + d[bi][0];
        float y = vb_s[vx][1] + d[bi][1];
        float z = vb_s[vx][2] + d[bi][2];
        #pragma unroll
        for (int e = 0; e < 10; e++) {
            float ex = ex_s[bb][e];
            x += ex * ed_s[vx][e];
            y += ex * ed_s[vx][10+e];
            z += ex * ed_s[vx][20+e];
        }
        px[bi] = x; py[bi] = y; pz[bi] = z;
    }

    // ---- phase C: T = sum_j w_j A_j, packed over batch pairs ----
    u64 t2[2][12];
    #pragma unroll
    for (int p = 0; p < 2; p++)
        #pragma unroll
        for (int q = 0; q < 12; q++) t2[p][q] = pack2(0.f, 0.f);

    for (int j0 = 0; j0 < J_; j0 += 8) {
        __syncthreads();
        // stage A2[jj][pair][q] with batch-pair interleave (lo=even b, hi=odd b)
        for (int i = tid; i < TB*8*3; i += 256) {
            int bb  = i / 24;
            int rem = i % 24;
            int jj  = rem / 3;
            int q4  = rem % 3;
            float4 val = make_float4(0.f, 0.f, 0.f, 0.f);
            if (j0 + jj < J_)
                val = *reinterpret_cast<const float4*>(&g_A[((size_t)(b0+bb)*J_ + (j0+jj))*12 + q4*4]);
            int pp = bb >> 1, h = bb & 1;
            float* dst = reinterpret_cast<float*>(&U.A2[jj][pp][0]);
            dst[(q4*4+0)*2 + h] = val.x;
            dst[(q4*4+1)*2 + h] = val.y;
            dst[(q4*4+2)*2 + h] = val.z;
            dst[(q4*4+3)*2 + h] = val.w;
        }
        __syncthreads();
        #pragma unroll
        for (int jj = 0; jj < 8; jj++) {
            u64 w2 = *reinterpret_cast<const u64*>(&W2_s[vx][j0 + jj]);   // (w,w); zero beyond J_
            #pragma unroll
            for (int p = 0; p < 2; p++) {
                const longlong2* ap = reinterpret_cast<const longlong2*>(&U.A2[jj][by + p*16][0]);
                #pragma unroll
                for (int q4 = 0; q4 < 6; q4++) {
                    longlong2 a = ap[q4];                 // two packed f32x2 values
                    t2[p][2*q4+0] = fma2(w2, (u64)a.x, t2[p][2*q4+0]);
                    t2[p][2*q4+1] = fma2(w2, (u64)a.y, t2[p][2*q4+1]);
                }
            }
        }
    }

    // ---- epilogue ----
    int v = v0 + vx;
    if (v < V_) {
        float yoff = g_yoff;
        #pragma unroll
        for (int p = 0; p < 2; p++) {
            float tq[2][12];
            #pragma unroll
            for (int q = 0; q < 12; q++) {
                float lo, hi;
                unpack2(t2[p][q], lo, hi);
                tq[0][q] = lo; tq[1][q] = hi;
            }
            #pragma unroll
            for (int h = 0; h < 2; h++) {
                int bi = p*2 + h;
                int b = b0 + 2*by + p*32 + h;
                float gx = gtrans[b*3+0], gy = gtrans[b*3+1], gz = gtrans[b*3+2];
                float x = px[bi], y = py[bi], z = pz[bi];
                float ox = tq[h][0]*x + tq[h][1]*y + tq[h][2] *z + tq[h][3]  + gx;
                float oy = tq[h][4]*x + tq[h][5]*y + tq[h][6] *z + tq[h][7]  + yoff + gy;
                float oz = tq[h][8]*x + tq[h][9]*y + tq[h][10]*z + tq[h][11] + gz;
                size_t o = ((size_t)b*V_ + v)*3;
                out[o+0] = ox; out[o+1] = oy; out[o+2] = oz;
            }
        }
    }
}

// ============== launch ==============
extern "C" void kernel_launch(void* const* d_in, const int* in_sizes, int n_in,
                              void* d_out, int out_size)
{
    const float* shape       = (const float*)d_in[0];   // (1,10)
    const float* body_pose   = (const float*)d_in[1];   // (B,21,3)
    const float* hand_pose   = (const float*)d_in[2];   // (B,30,3)
    const float* head_pose   = (const float*)d_in[3];   // (B,3,3)
    const float* expression  = (const float*)d_in[4];   // (B,10)
    const float* pelvis_rot  = (const float*)d_in[5];   // (B,3)
    const float* gtrans      = (const float*)d_in[6];   // (B,3)
    const float* v_template  = (const float*)d_in[7];   // (V,3)
    const float* shapedirs   = (const float*)d_in[8];   // (V,3,10)
    const float* exprdirs    = (const float*)d_in[9];   // (V,3,10)
    const float* posedirs    = (const float*)d_in[10];  // (486, V*3)
    const float* lbs_weights = (const float*)d_in[11];  // (V,J)
    const float* J_regressor = (const float*)d_in[12];  // (J,V)
    const float* hand_mean   = (const float*)d_in[13];  // (2,45)
    float* out = (float*)d_out;

    k_vbase<<<(V3_ + 255)/256, 256>>>(v_template, shapedirs, shape);
    k_ymin<<<1, 1024>>>(v_template);
    k_jreg<<<J_, 128>>>(J_regressor, exprdirs);
    k_pose<<<B_, 64>>>(body_pose, hand_pose, head_pose, pelvis_rot, hand_mean, expression);
    dim3 grid((V_ + TV - 1)/TV, B_/TB);
    k_main<<<grid, 256>>>(posedirs, lbs_weights, exprdirs, expression, gtrans, out);
}

// round 9
// speedup vs baseline: 1.0045x; 1.0045x over previous
#include <cuda_runtime.h>
#include <math.h>

#define V_   10475
#define J_   55
#define B_   512
#define V3_  (V_*3)     // 31425
#define K486 486

#define TV 16   // vertices per block (main kernel)
#define TB 64   // batches per block (= 32 pairs)
#define KT 32   // K-chunk

typedef unsigned long long u64;

__device__ __forceinline__ u64 pack2(float lo, float hi) {
    u64 r;
    asm("mov.b64 %0, {%1, %2};" : "=l"(r) : "r"(__float_as_uint(lo)), "r"(__float_as_uint(hi)));
    return r;
}
__device__ __forceinline__ void unpack2(u64 v, float& lo, float& hi) {
    unsigned int a, b;
    asm("mov.b64 {%0, %1}, %2;" : "=r"(a), "=r"(b) : "l"(v));
    lo = __uint_as_float(a); hi = __uint_as_float(b);
}
__device__ __forceinline__ u64 fma2(u64 a, u64 b, u64 c) {
    u64 d;
    asm("fma.rn.f32x2 %0, %1, %2, %3;" : "=l"(d) : "l"(a), "l"(b), "l"(c));
    return d;
}

// -------- device scratch (no allocations allowed) --------
__device__ __align__(16) float g_vbase[V_*3];
__device__ float g_yoff;
__device__ float g_Jbase[J_*3];
__device__ float g_JE[J_*3*10];
__device__ __align__(16) float g_pf_t[K486*B_];     // transposed pose_feature: [k][b]
__device__ __align__(16) float g_A[B_*J_*12];       // per-joint 3x4 skinning matrices

// ============== Kernel 1: vbase = v_template + shapedirs @ shape ==============
__global__ void k_vbase(const float* __restrict__ vt,
                        const float* __restrict__ shapedirs,
                        const float* __restrict__ shape)
{
    int i = blockIdx.x*256 + threadIdx.x;
    if (i < V3_) {
        float acc = vt[i];
        #pragma unroll
        for (int s = 0; s < 10; s++) acc += shape[s] * shapedirs[i*10 + s];
        g_vbase[i] = acc;
    }
}

// ============== Kernel 2: y offset = -min(v_template[:,1]) ==============
__global__ void k_ymin(const float* __restrict__ vt)
{
    __shared__ float red[1024];
    float m = 1e30f;
    for (int v = threadIdx.x; v < V_; v += 1024) m = fminf(m, vt[v*3 + 1]);
    red[threadIdx.x] = m;
    __syncthreads();
    for (int s = 512; s > 0; s >>= 1) {
        if (threadIdx.x < s) red[threadIdx.x] = fminf(red[threadIdx.x], red[threadIdx.x + s]);
        __syncthreads();
    }
    if (threadIdx.x == 0) g_yoff = -red[0];
}

// ============== Kernel 3: Jbase(j,c) and JE(j,c,e) = JR @ [vbase | exprdirs] ==============
__global__ void k_jreg(const float* __restrict__ JR,
                       const float* __restrict__ exprdirs)
{
    int j = blockIdx.x;
    int tid = threadIdx.x;            // 128 threads
    float acc[33];
    #pragma unroll
    for (int i = 0; i < 33; i++) acc[i] = 0.f;

    for (int v = tid; v < V_; v += 128) {
        float jr = JR[j*V_ + v];
        acc[0] += jr * g_vbase[v*3 + 0];
        acc[1] += jr * g_vbase[v*3 + 1];
        acc[2] += jr * g_vbase[v*3 + 2];
        const float* ed = &exprdirs[v*30];
        #pragma unroll
        for (int i = 0; i < 30; i++) acc[3+i] += jr * ed[i];
    }
    __shared__ float red[4][33];
    int lane = tid & 31, w = tid >> 5;
    #pragma unroll
    for (int i = 0; i < 33; i++) {
        float v = acc[i];
        for (int off = 16; off > 0; off >>= 1) v += __shfl_down_sync(0xffffffffu, v, off);
        if (lane == 0) red[w][i] = v;
    }
    __syncthreads();
    if (tid < 33) {
        float s = red[0][tid] + red[1][tid] + red[2][tid] + red[3][tid];
        if (tid < 3) g_Jbase[j*3 + tid] = s;
        else         g_JE[j*30 + (tid-3)] = s;
    }
}

// ============== Kernel 4: per-batch rodrigues, pose_feature, joints, chain, A ==============
__global__ void k_pose(const float* __restrict__ body,
                       const float* __restrict__ hand,
                       const float* __restrict__ head,
                       const float* __restrict__ pelvis,
                       const float* __restrict__ hand_mean,
                       const float* __restrict__ expression)
{
    int b = blockIdx.x;
    int tid = threadIdx.x;            // 64 threads
    __shared__ float R_s[J_][9];
    __shared__ float jnt[J_][3];

    if (tid < J_) {
        float r0, r1, r2;
        if (tid == 0) {
            r0 = pelvis[b*3+0]; r1 = pelvis[b*3+1]; r2 = pelvis[b*3+2];
        } else if (tid <= 21) {
            int i = tid - 1;
            r0 = body[(b*21+i)*3+0]; r1 = body[(b*21+i)*3+1]; r2 = body[(b*21+i)*3+2];
        } else if (tid <= 24) {
            int i = tid - 22;
            r0 = head[(b*3+i)*3+0]; r1 = head[(b*3+i)*3+1]; r2 = head[(b*3+i)*3+2];
        } else {
            int h = tid - 25;
            r0 = hand[(b*30+h)*3+0] + hand_mean[h*3+0];
            r1 = hand[(b*30+h)*3+1] + hand_mean[h*3+1];
            r2 = hand[(b*30+h)*3+2] + hand_mean[h*3+2];
        }
        float a2  = r0*r0 + r1*r1 + r2*r2 + 1e-12f;
        float ang = sqrtf(a2);
        float inv = 1.0f / ang;
        float kx = r0*inv, ky = r1*inv, kz = r2*inv;
        float s = sinf(ang), c = cosf(ang);
        float t1 = 1.0f - c;
        float R[9];
        R[0] = c + t1*kx*kx;     R[1] = t1*kx*ky - s*kz;  R[2] = t1*kx*kz + s*ky;
        R[3] = t1*kx*ky + s*kz;  R[4] = c + t1*ky*ky;     R[5] = t1*ky*kz - s*kx;
        R[6] = t1*kx*kz - s*ky;  R[7] = t1*ky*kz + s*kx;  R[8] = c + t1*kz*kz;
        #pragma unroll
        for (int i = 0; i < 9; i++) R_s[tid][i] = R[i];
        if (tid >= 1) {
            #pragma unroll
            for (int i = 0; i < 9; i++) {
                float d = (i == 0 || i == 4 || i == 8) ? 1.0f : 0.0f;
                g_pf_t[((tid-1)*9 + i)*B_ + b] = R[i] - d;
            }
        }
        #pragma unroll
        for (int cc = 0; cc < 3; cc++) {
            float acc = g_Jbase[tid*3 + cc];
            #pragma unroll
            for (int e = 0; e < 10; e++)
                acc += expression[b*10 + e] * g_JE[(tid*3 + cc)*10 + e];
            jnt[tid][cc] = acc;
        }
    }
    __syncthreads();

    if (tid < 3) {
        int r = tid;
        float g0 = R_s[0][r*3+0], g1 = R_s[0][r*3+1], g2 = R_s[0][r*3+2], g3 = jnt[0][r];
        g_A[(b*J_ + 0)*12 + r*4 + 0] = g0;
        g_A[(b*J_ + 0)*12 + r*4 + 1] = g1;
        g_A[(b*J_ + 0)*12 + r*4 + 2] = g2;
        g_A[(b*J_ + 0)*12 + r*4 + 3] = g3 - (g0*jnt[0][0] + g1*jnt[0][1] + g2*jnt[0][2]);
        for (int j = 1; j < J_; j++) {
            float t0 = jnt[j][0] - jnt[j-1][0];
            float t1 = jnt[j][1] - jnt[j-1][1];
            float t2 = jnt[j][2] - jnt[j-1][2];
            float n0 = g0*R_s[j][0] + g1*R_s[j][3] + g2*R_s[j][6];
            float n1 = g0*R_s[j][1] + g1*R_s[j][4] + g2*R_s[j][7];
            float n2 = g0*R_s[j][2] + g1*R_s[j][5] + g2*R_s[j][8];
            float n3 = g0*t0 + g1*t1 + g2*t2 + g3;
            g0 = n0; g1 = n1; g2 = n2; g3 = n3;
            g_A[(b*J_ + j)*12 + r*4 + 0] = g0;
            g_A[(b*J_ + j)*12 + r*4 + 1] = g1;
            g_A[(b*J_ + j)*12 + r*4 + 2] = g2;
            g_A[(b*J_ + j)*12 + r*4 + 3] = g3 - (g0*jnt[j][0] + g1*jnt[j][1] + g2*jnt[j][2]);
        }
    }
}

// ============== Kernel 5: fused GEMM + expression + LBS + epilogue, f32x2 packed ==============
// Batch-pair packing: pair pp holds batches (b0+2pp, b0+2pp+1). Thread (vx, by)
// owns vertex vx and pairs {by, by+16} -> tile-local batches {2by,2by+1,2by+32,2by+33}.
__global__ void __launch_bounds__(256, 2)
k_main(const float* __restrict__ posedirs,
       const float* __restrict__ lbsw,
       const float* __restrict__ exprdirs,
       const float* __restrict__ expression,
       const float* __restrict__ gtrans,
       float* __restrict__ out)
{
    // phase-A tiles and phase-C tiles never live at the same time -> union
    __shared__ __align__(16) union {
        struct {
            float2 pf2[32][34];     // [pair][k], padded row (34*8=272B, 16B-aligned rows)
            float4 pd4[KT][TV];     // [k][vertex] = (x,y,z,unused)
        } a;
        float2 A2[8][32][12];       // [jj][pair][q]: lo=even batch, hi=odd batch
    } U;
    __shared__ float  ed_s[TV][30];
    __shared__ float  ex_s[TB][10];
    __shared__ __align__(16) float2 W2_s[TV][56];   // duplicated weights (w,w)
    __shared__ float  vb_s[TV][3];

    const int v0 = blockIdx.x * TV;
    const int b0 = blockIdx.y * TB;
    const int tid = threadIdx.x;
    const int vx = tid & 15;
    const int by = tid >> 4;       // 0..15

    // ---- one-time tile loads ----
    for (int i = tid; i < TV*56; i += 256) {
        int vv = i / 56, j = i % 56;
        float w = 0.f;
        if (j < J_ && v0 + vv < V_) w = lbsw[(v0+vv)*J_ + j];
        W2_s[vv][j] = make_float2(w, w);
    }
    for (int i = tid; i < TV*30; i += 256) {
        int vv = i / 30, e = i % 30;
        ed_s[vv][e] = (v0 + vv < V_) ? exprdirs[(v0+vv)*30 + e] : 0.f;
    }
    for (int i = tid; i < TB*10; i += 256)
        ex_s[i/10][i%10] = expression[(b0 + i/10)*10 + (i%10)];
    for (int i = tid; i < TV*3; i += 256)
        vb_s[i/3][i%3] = (v0 + i/3 < V_) ? g_vbase[(v0 + i/3)*3 + (i%3)] : 0.f;

    // ---- phase A: delta(pair, c) = PF @ posedirs, packed over batch pairs ----
    u64 acc[2][3];
    #pragma unroll
    for (int p = 0; p < 2; p++)
        #pragma unroll
        for (int c = 0; c < 3; c++) acc[p][c] = pack2(0.f, 0.f);

    for (int k0 = 0; k0 < K486; k0 += KT) {
        __syncthreads();
        // pf: [pair][k] float2, read batch-pairs straight out of g_pf_t
        for (int i = tid; i < 32*KT; i += 256) {
            int k = i >> 5, pp = i & 31;
            float2 v = make_float2(0.f, 0.f);
            if (k0 + k < K486)
                v = *reinterpret_cast<const float2*>(&g_pf_t[(k0+k)*B_ + b0 + 2*pp]);
            U.a.pf2[pp][k] = v;
        }
        // pd: [k][vertex] float4 (x,y,z,pad)
        for (int i = tid; i < KT*TV*3; i += 256) {
            int k = i / 48, c = i % 48;
            int vv = c / 3, cc = c % 3;
            int col = v0*3 + c;
            float val = (k0 + k < K486 && col < V3_) ? posedirs[(size_t)(k0+k)*V3_ + col] : 0.f;
            reinterpret_cast<float*>(&U.a.pd4[k][vv])[cc] = val;
        }
        __syncthreads();

        #pragma unroll
        for (int kk = 0; kk < KT; kk += 2) {
            float4 pA = U.a.pd4[kk][vx];
            float4 pB = U.a.pd4[kk+1][vx];
            longlong2 f0 = *reinterpret_cast<const longlong2*>(&U.a.pf2[by][kk]);      // pair by:    k, k+1
            longlong2 f1 = *reinterpret_cast<const longlong2*>(&U.a.pf2[by+16][kk]);   // pair by+16: k, k+1

            u64 P0a = pack2(pA.x, pA.x), P1a = pack2(pA.y, pA.y), P2a = pack2(pA.z, pA.z);
            u64 P0b = pack2(pB.x, pB.x), P1b = pack2(pB.y, pB.y), P2b = pack2(pB.z, pB.z);

            u64 f0a = (u64)f0.x, f0b = (u64)f0.y;
            u64 f1a = (u64)f1.x, f1b = (u64)f1.y;

            acc[0][0] = fma2(f0a, P0a, acc[0][0]);
            acc[0][1] = fma2(f0a, P1a, acc[0][1]);
            acc[0][2] = fma2(f0a, P2a, acc[0][2]);
            acc[1][0] = fma2(f1a, P0a, acc[1][0]);
            acc[1][1] = fma2(f1a, P1a, acc[1][1]);
            acc[1][2] = fma2(f1a, P2a, acc[1][2]);
            acc[0][0] = fma2(f0b, P0b, acc[0][0]);
            acc[0][1] = fma2(f0b, P1b, acc[0][1]);
            acc[0][2] = fma2(f0b, P2b, acc[0][2]);
            acc[1][0] = fma2(f1b, P0b, acc[1][0]);
            acc[1][1] = fma2(f1b, P1b, acc[1][1]);
            acc[1][2] = fma2(f1b, P2b, acc[1][2]);
        }
    }

    // unpack delta: bi -> tile-local batch {2by, 2by+1, 2by+32, 2by+33}
    float d[4][3];
    #pragma unroll
    for (int p = 0; p < 2; p++)
        #pragma unroll
        for (int c = 0; c < 3; c++) {
            float lo, hi;
            unpack2(acc[p][c], lo, hi);
            d[p*2+0][c] = lo; d[p*2+1][c] = hi;
        }

    // ---- phase B: v_posed = vbase + delta + exprdirs . expression ----
    float px[4], py[4], pz[4];
    #pragma unroll
    for (int bi = 0; bi < 4; bi++) {
        int bb = 2*by + (bi >> 1)*32 + (bi & 1);
        float x = vb_s[vx][0] + d[bi][0];
        float y = vb_s[vx][1] + d[bi][1];
        float z = vb_s[vx][2] + d[bi][2];
        #pragma unroll
        for (int e = 0; e < 10; e++) {
            float ex = ex_s[bb][e];
            x += ex * ed_s[vx][e];
            y += ex * ed_s[vx][10+e];
            z += ex * ed_s[vx][20+e];
        }
        px[bi] = x; py[bi] = y; pz[bi] = z;
    }

    // ---- phase C: T = sum_j w_j A_j, packed over batch pairs ----
    u64 t2[2][12];
    #pragma unroll
    for (int p = 0; p < 2; p++)
        #pragma unroll
        for (int q = 0; q < 12; q++) t2[p][q] = pack2(0.f, 0.f);

    for (int j0 = 0; j0 < J_; j0 += 8) {
        __syncthreads();
        // stage A2[jj][pair][q] with batch-pair interleave (lo=even b, hi=odd b)
        for (int i = tid; i < TB*8*3; i += 256) {
            int bb  = i / 24;
            int rem = i % 24;
            int jj  = rem / 3;
            int q4  = rem % 3;
            float4 val = make_float4(0.f, 0.f, 0.f, 0.f);
            if (j0 + jj < J_)
                val = *reinterpret_cast<const float4*>(&g_A[((size_t)(b0+bb)*J_ + (j0+jj))*12 + q4*4]);
            int pp = bb >> 1, h = bb & 1;
            float* dst = reinterpret_cast<float*>(&U.A2[jj][pp][0]);
            dst[(q4*4+0)*2 + h] = val.x;
            dst[(q4*4+1)*2 + h] = val.y;
            dst[(q4*4+2)*2 + h] = val.z;
            dst[(q4*4+3)*2 + h] = val.w;
        }
        __syncthreads();
        #pragma unroll
        for (int jj = 0; jj < 8; jj++) {
            u64 w2 = *reinterpret_cast<const u64*>(&W2_s[vx][j0 + jj]);   // (w,w); zero beyond J_
            #pragma unroll
            for (int p = 0; p < 2; p++) {
                const longlong2* ap = reinterpret_cast<const longlong2*>(&U.A2[jj][by + p*16][0]);
                #pragma unroll
                for (int q4 = 0; q4 < 6; q4++) {
                    longlong2 a = ap[q4];                 // two packed f32x2 values
                    t2[p][2*q4+0] = fma2(w2, (u64)a.x, t2[p][2*q4+0]);
                    t2[p][2*q4+1] = fma2(w2, (u64)a.y, t2[p][2*q4+1]);
                }
            }
        }
    }

    // ---- epilogue ----
    int v = v0 + vx;
    if (v < V_) {
        float yoff = g_yoff;
        #pragma unroll
        for (int p = 0; p < 2; p++) {
            float tq[2][12];
            #pragma unroll
            for (int q = 0; q < 12; q++) {
                float lo, hi;
                unpack2(t2[p][q], lo, hi);
                tq[0][q] = lo; tq[1][q] = hi;
            }
            #pragma unroll
            for (int h = 0; h < 2; h++) {
                int bi = p*2 + h;
                int b = b0 + 2*by + p*32 + h;
                float gx = gtrans[b*3+0], gy = gtrans[b*3+1], gz = gtrans[b*3+2];
                float x = px[bi], y = py[bi], z = pz[bi];
                float ox = tq[h][0]*x + tq[h][1]*y + tq[h][2] *z + tq[h][3]  + gx;
                float oy = tq[h][4]*x + tq[h][5]*y + tq[h][6] *z + tq[h][7]  + yoff + gy;
                float oz = tq[h][8]*x + tq[h][9]*y + tq[h][10]*z + tq[h][11] + gz;
                size_t o = ((size_t)b*V_ + v)*3;
                out[o+0] = ox; out[o+1] = oy; out[o+2] = oz;
            }
        }
    }
}

// ============== launch ==============
extern "C" void kernel_launch(void* const* d_in, const int* in_sizes, int n_in,
                              void* d_out, int out_size)
{
    const float* shape       = (const float*)d_in[0];   // (1,10)
    const float* body_pose   = (const float*)d_in[1];   // (B,21,3)
    const float* hand_pose   = (const float*)d_in[2];   // (B,30,3)
    const float* head_pose   = (const float*)d_in[3];   // (B,3,3)
    const float* expression  = (const float*)d_in[4];   // (B,10)
    const float* pelvis_rot  = (const float*)d_in[5];   // (B,3)
    const float* gtrans      = (const float*)d_in[6];   // (B,3)
    const float* v_template  = (const float*)d_in[7];   // (V,3)
    const float* shapedirs   = (const float*)d_in[8];   // (V,3,10)
    const float* exprdirs    = (const float*)d_in[9];   // (V,3,10)
    const float* posedirs    = (const float*)d_in[10];  // (486, V*3)
    const float* lbs_weights = (const float*)d_in[11];  // (V,J)
    const float* J_regressor = (const float*)d_in[12];  // (J,V)
    const float* hand_mean   = (const float*)d_in[13];  // (2,45)
    float* out = (float*)d_out;

    k_vbase<<<(V3_ + 255)/256, 256>>>(v_template, shapedirs, shape);
    k_ymin<<<1, 1024>>>(v_template);
    k_jreg<<<J_, 128>>>(J_regressor, exprdirs);
    k_pose<<<B_, 64>>>(body_pose, hand_pose, head_pose, pelvis_rot, hand_mean, expression);
    dim3 grid((V_ + TV - 1)/TV, B_/TB);
    k_main<<<grid, 256>>>(posedirs, lbs_weights, exprdirs, expression, gtrans, out);
}